// round 5
// baseline (speedup 1.0000x reference)
#include <cuda_runtime.h>
#include <cuda_fp16.h>
#include <math.h>

#define NB 8192
#define BB 64
#define DD 5
#define NE (NB*DD)      // 40960 neighbor edges
#define NT (NB*BB)      // 524288 (node, batch) rows
#define HC 16

// ---------------- device scratch (no runtime allocation allowed) ------------
__device__ __half g_xl [(size_t)NT * HC];   // 16.8 MB, layout (n,b,hc) fp16 (buffer A)
__device__ __half g_xl2[(size_t)NT * HC];   // 16.8 MB                      (buffer B)
__device__ float  g_h  [(size_t)NT * HC];   // 33.5 MB fp32
__device__ float  g_pool[BB * HC];
__device__ float  g_agg[BB * 64];
__device__ int    g_off[NB + 1];
__device__ int    g_csr[NE];

// ---------------- fp16 row <-> fp32 helpers --------------------------------
__device__ __forceinline__ void row_h2f(uint4 u0, uint4 u1, float* v) {
    float2 f;
    f = __half22float2(*reinterpret_cast<__half2*>(&u0.x)); v[0]  = f.x; v[1]  = f.y;
    f = __half22float2(*reinterpret_cast<__half2*>(&u0.y)); v[2]  = f.x; v[3]  = f.y;
    f = __half22float2(*reinterpret_cast<__half2*>(&u0.z)); v[4]  = f.x; v[5]  = f.y;
    f = __half22float2(*reinterpret_cast<__half2*>(&u0.w)); v[6]  = f.x; v[7]  = f.y;
    f = __half22float2(*reinterpret_cast<__half2*>(&u1.x)); v[8]  = f.x; v[9]  = f.y;
    f = __half22float2(*reinterpret_cast<__half2*>(&u1.y)); v[10] = f.x; v[11] = f.y;
    f = __half22float2(*reinterpret_cast<__half2*>(&u1.z)); v[12] = f.x; v[13] = f.y;
    f = __half22float2(*reinterpret_cast<__half2*>(&u1.w)); v[14] = f.x; v[15] = f.y;
}

__device__ __forceinline__ void row_f2h(const float* v, uint4& u0, uint4& u1) {
    __half2 h;
    h = __floats2half2_rn(v[0],  v[1]);  u0.x = *reinterpret_cast<unsigned*>(&h);
    h = __floats2half2_rn(v[2],  v[3]);  u0.y = *reinterpret_cast<unsigned*>(&h);
    h = __floats2half2_rn(v[4],  v[5]);  u0.z = *reinterpret_cast<unsigned*>(&h);
    h = __floats2half2_rn(v[6],  v[7]);  u0.w = *reinterpret_cast<unsigned*>(&h);
    h = __floats2half2_rn(v[8],  v[9]);  u1.x = *reinterpret_cast<unsigned*>(&h);
    h = __floats2half2_rn(v[10], v[11]); u1.y = *reinterpret_cast<unsigned*>(&h);
    h = __floats2half2_rn(v[12], v[13]); u1.z = *reinterpret_cast<unsigned*>(&h);
    h = __floats2half2_rn(v[14], v[15]); u1.w = *reinterpret_cast<unsigned*>(&h);
}

// ---------------- one-kernel reverse-CSR build -----------------------------
__global__ __launch_bounds__(1024)
void csr_build_kernel(const int* __restrict__ neighbors) {
    __shared__ int scnt[NB];          // 32 KB counters, later reused as cursors
    __shared__ int wsum[32];
    int t = threadIdx.x;
    if (t < BB * HC) g_pool[t] = 0.f;
#pragma unroll
    for (int i = 0; i < NB / 1024; i++) scnt[t + i * 1024] = 0;
    __syncthreads();

    for (int e = t; e < NE; e += 1024) atomicAdd(&scnt[neighbors[e]], 1);
    __syncthreads();

    int v[8];
    int s = 0;
#pragma unroll
    for (int i = 0; i < 8; i++) { v[i] = scnt[t * 8 + i]; s += v[i]; }
    unsigned lane = t & 31, wid = t >> 5;
    int x = s;
#pragma unroll
    for (int o = 1; o < 32; o <<= 1) {
        int y = __shfl_up_sync(0xffffffffu, x, o);
        if (lane >= (unsigned)o) x += y;
    }
    if (lane == 31) wsum[wid] = x;
    __syncthreads();
    if (wid == 0) {
        int w = wsum[lane];
#pragma unroll
        for (int o = 1; o < 32; o <<= 1) {
            int y = __shfl_up_sync(0xffffffffu, w, o);
            if (lane >= (unsigned)o) w += y;
        }
        wsum[lane] = w;
    }
    __syncthreads();
    int excl = x - s + (wid ? wsum[wid - 1] : 0);
    int run = excl;
#pragma unroll
    for (int i = 0; i < 8; i++) {
        g_off[t * 8 + i] = run;
        scnt[t * 8 + i] = run;        // reuse as fill cursor
        run += v[i];
    }
    if (t == 1023) g_off[NB] = run;
    __syncthreads();

    for (int e = t; e < NE; e += 1024) {
        int dst = neighbors[e];
        int pos = atomicAdd(&scnt[dst], 1);
        g_csr[pos] = e / DD;          // source node of edge e
    }
}

// ---------------- layer-0 xl projection: g_xl = fp16(x @ Wl0) --------------
__global__ __launch_bounds__(256)
void xl0_kernel(const float* __restrict__ xin, const float* __restrict__ Wl) {
    __shared__ float sW[256];
    int t = threadIdx.x;
    sW[t] = Wl[t];
    __syncthreads();

    int idx = blockIdx.x * 256 + t;      // n*64 + b
    int n = idx >> 6, b = idx & 63;
    const float4* p4 = (const float4*)(xin + ((size_t)b * NB + n) * HC);
    float in[16];
#pragma unroll
    for (int i = 0; i < 4; i++) {
        float4 v = __ldcs(p4 + i);                    // streaming read of x
        in[4 * i] = v.x; in[4 * i + 1] = v.y; in[4 * i + 2] = v.z; in[4 * i + 3] = v.w;
    }
    float ol[16];
#pragma unroll
    for (int o = 0; o < 16; o++) ol[o] = 0.f;
#pragma unroll
    for (int f = 0; f < 16; f++) {
        float a = in[f];
#pragma unroll
        for (int o = 0; o < 16; o++) ol[o] = fmaf(a, sW[f * 16 + o], ol[o]);
    }
    uint4 u0, u1;
    row_f2h(ol, u0, u1);
    uint4* pl = (uint4*)(g_xl + (size_t)idx * HC);
    pl[0] = u0; pl[1] = u1;
}

// ---------------- fused GATv2 layer ----------------------------------------
template <int IN, bool FIRST, bool LAST>
__global__ __launch_bounds__(128, 5)
void gat_fused_kernel(const float* __restrict__ hin,   // only used when FIRST (x, (b,n,f))
                      const float* __restrict__ Wr,
                      const float* __restrict__ attw,
                      const float* __restrict__ bias,
                      const float* __restrict__ Wln) { // next layer's Wl (null if LAST)
    __shared__ float sWr[256], sWln[256], satt[16], sbias[16];
    int t = threadIdx.x;
    sWr[t] = Wr[t];   sWr[t + 128] = Wr[t + 128];
    if (!LAST) { sWln[t] = Wln[t]; sWln[t + 128] = Wln[t + 128]; }
    if (t < 16) { satt[t] = attw[t]; sbias[t] = bias[t]; }
    __syncthreads();

    const __half* __restrict__ xlin  = (IN == 0) ? g_xl : g_xl2;
    __half*       __restrict__ xlout = (IN == 0) ? g_xl2 : g_xl;

    int idx = blockIdx.x * 128 + t;      // n*64 + b
    int n = idx >> 6, b = idx & 63;

    // ---- load h row, compute xrv = h @ Wr -------------------------------
    const float4* hp4 = FIRST ? (const float4*)(hin + ((size_t)b * NB + n) * HC)
                              : (const float4*)(g_h + (size_t)idx * HC);
    float hv[16];
#pragma unroll
    for (int i = 0; i < 4; i++) {
        float4 v = FIRST ? __ldcs(hp4 + i) : hp4[i];
        hv[4 * i] = v.x; hv[4 * i + 1] = v.y; hv[4 * i + 2] = v.z; hv[4 * i + 3] = v.w;
    }
    float xrv[16];
#pragma unroll
    for (int o = 0; o < 16; o++) xrv[o] = 0.f;
#pragma unroll
    for (int f = 0; f < 16; f++) {
        float a = hv[f];
#pragma unroll
        for (int o = 0; o < 16; o++) xrv[o] = fmaf(a, sWr[f * 16 + o], xrv[o]);
    }

    // ---- self edge initializes online softmax ---------------------------
    float vv[16];
    {
        const uint4* pl = (const uint4*)(xlin + (size_t)idx * HC);
        row_h2f(pl[0], pl[1], vv);
    }
    float m[4], s[4], acc[16];
#pragma unroll
    for (int h = 0; h < 4; h++) {
        float l = 0.f;
#pragma unroll
        for (int c = 0; c < 4; c++) {
            float tsum = vv[h * 4 + c] + xrv[h * 4 + c];
            tsum = tsum > 0.f ? tsum : 0.2f * tsum;      // leaky_relu(0.2)
            l = fmaf(tsum, satt[h * 4 + c], l);
        }
        m[h] = l; s[h] = 1.f;
    }
#pragma unroll
    for (int j = 0; j < 16; j++) acc[j] = vv[j];

    // ---- incoming-edge loop with 2-deep prefetch (fp16 rows, 8 regs/stage)
    int beg = g_off[n], end = g_off[n + 1];
    uint4 A0, A1, B0, B1;
    A0 = A1 = B0 = B1 = make_uint4(0u, 0u, 0u, 0u);
    if (beg < end) {
        const uint4* p = (const uint4*)(xlin + ((size_t)g_csr[beg] * BB + b) * HC);
        A0 = p[0]; A1 = p[1];
    }
    if (beg + 1 < end) {
        const uint4* p = (const uint4*)(xlin + ((size_t)g_csr[beg + 1] * BB + b) * HC);
        B0 = p[0]; B1 = p[1];
    }
    for (int e = beg; e < end; e++) {
        uint4 C0, C1;
        C0 = C1 = make_uint4(0u, 0u, 0u, 0u);
        if (e + 2 < end) {
            const uint4* p = (const uint4*)(xlin + ((size_t)g_csr[e + 2] * BB + b) * HC);
            C0 = p[0]; C1 = p[1];
        }
        row_h2f(A0, A1, vv);
#pragma unroll
        for (int h = 0; h < 4; h++) {
            float l = 0.f;
#pragma unroll
            for (int c = 0; c < 4; c++) {
                float tsum = vv[h * 4 + c] + xrv[h * 4 + c];
                tsum = tsum > 0.f ? tsum : 0.2f * tsum;
                l = fmaf(tsum, satt[h * 4 + c], l);
            }
            float nm = fmaxf(m[h], l);
            float sc = __expf(m[h] - nm);
            float w  = __expf(l - nm);
            s[h] = fmaf(s[h], sc, w);
            m[h] = nm;
#pragma unroll
            for (int c = 0; c < 4; c++)
                acc[h * 4 + c] = fmaf(acc[h * 4 + c], sc, w * vv[h * 4 + c]);
        }
        A0 = B0; A1 = B1;
        B0 = C0; B1 = C1;
    }

    // ---- finalize h row --------------------------------------------------
#pragma unroll
    for (int h = 0; h < 4; h++) {
        float inv = 1.f / (s[h] + 1e-16f);
#pragma unroll
        for (int c = 0; c < 4; c++)
            hv[h * 4 + c] = acc[h * 4 + c] * inv + sbias[h * 4 + c];
    }
    {
        float4* po = (float4*)(g_h + (size_t)idx * HC);
#pragma unroll
        for (int i = 0; i < 4; i++)
            po[i] = make_float4(hv[4 * i], hv[4 * i + 1], hv[4 * i + 2], hv[4 * i + 3]);
    }

    // ---- fused next-layer xl projection (fp16 store) ---------------------
    if (!LAST) {
        float ol[16];
#pragma unroll
        for (int o = 0; o < 16; o++) ol[o] = 0.f;
#pragma unroll
        for (int f = 0; f < 16; f++) {
            float a = hv[f];
#pragma unroll
            for (int o = 0; o < 16; o++) ol[o] = fmaf(a, sWln[f * 16 + o], ol[o]);
        }
        uint4 u0, u1;
        row_f2h(ol, u0, u1);
        uint4* pl = (uint4*)(xlout + (size_t)idx * HC);
        pl[0] = u0; pl[1] = u1;
    }
}

// ---------------- mean-pool over nodes (phase 1: partial sums) -------------
__global__ __launch_bounds__(256)
void pool1_kernel() {
    int b = blockIdx.x >> 3;       // 64 batches
    int chunk = blockIdx.x & 7;    // 8 node chunks of 1024
    int t = threadIdx.x;
    int f = t & 15, g = t >> 4;    // 16 groups
    float sum = 0.f;
    int n0 = chunk * 1024 + g;
    for (int k = 0; k < 64; k++) {
        int n = n0 + k * 16;
        sum += g_h[((size_t)n * BB + b) * HC + f];
    }
    __shared__ float red[256];
    red[t] = sum;
    __syncthreads();
    for (int st = 128; st >= 16; st >>= 1) {
        if (t < st) red[t] += red[t + st];
        __syncthreads();
    }
    if (t < 16) atomicAdd(&g_pool[b * 16 + t], red[t]);
}

// ---------------- agg MLP (phase 2) ---------------------------------------
__global__ void pool2_kernel(const float* __restrict__ Wg1, const float* __restrict__ bg1,
                             const float* __restrict__ Wg2, const float* __restrict__ bg2) {
    int b = blockIdx.x;
    int t = threadIdx.x;   // 64 threads
    __shared__ float pool[16], g1[32];
    if (t < 16) pool[t] = g_pool[b * 16 + t] * (1.f / (float)NB);
    __syncthreads();
    if (t < 32) {
        float s = bg1[t];
#pragma unroll
        for (int ff = 0; ff < 16; ff++) s = fmaf(pool[ff], Wg1[ff * 32 + t], s);
        g1[t] = tanhf(s);
    }
    __syncthreads();
    float s = bg2[t];
#pragma unroll
    for (int k = 0; k < 32; k++) s = fmaf(g1[k], Wg2[k * 64 + t], s);
    g_agg[b * 64 + t] = tanhf(s);
}

// ---------------- edge scorer MLP (B x 3 x D items) ------------------------
__device__ __forceinline__ void acc_feat(float* acc1, const float* __restrict__ We1,
                                         int i, float val) {
#pragma unroll
    for (int o = 0; o < 16; o++)
        acc1[o] = fmaf(val, We1[i * 16 + o], acc1[o]);
}

__global__ void scorer_kernel(const int* __restrict__ agent_nodes,
                              const int* __restrict__ neighbors,
                              const float* __restrict__ We1, const float* __restrict__ be1,
                              const float* __restrict__ We2, const float* __restrict__ be2,
                              const float* __restrict__ We3, const float* __restrict__ be3,
                              float* __restrict__ out) {
    int i = blockIdx.x * blockDim.x + threadIdx.x;
    if (i >= BB * 3 * DD) return;
    int b = i / (3 * DD);
    int r = i % (3 * DD);
    int tk = r / DD;
    int d  = r % DD;
    int an = agent_nodes[b];
    int tg = neighbors[an * DD + d];

    float acc1[16];
#pragma unroll
    for (int o = 0; o < 16; o++) acc1[o] = be1[o];

#pragma unroll
    for (int ff = 0; ff < 16; ff++)                         // source features [0,16)
        acc_feat(acc1, We1, ff, g_h[((size_t)an * BB + b) * HC + ff]);
    acc_feat(acc1, We1, 16, tk == 0 ? 1.f : 0.f);           // token one-hot [16,19)
    acc_feat(acc1, We1, 17, tk == 1 ? 1.f : 0.f);
    acc_feat(acc1, We1, 18, tk == 2 ? 1.f : 0.f);
#pragma unroll
    for (int ff = 0; ff < 16; ff++)                         // target features [19,35)
        acc_feat(acc1, We1, 19 + ff, g_h[((size_t)tg * BB + b) * HC + ff]);
#pragma unroll
    for (int k = 0; k < 64; k++)                            // agg features [35,99)
        acc_feat(acc1, We1, 35 + k, g_agg[b * 64 + k]);

    float e1[16];
#pragma unroll
    for (int o = 0; o < 16; o++) e1[o] = tanhf(acc1[o]);

    float e2[8];
#pragma unroll
    for (int o2 = 0; o2 < 8; o2++) {
        float s = be2[o2];
#pragma unroll
        for (int o = 0; o < 16; o++) s = fmaf(e1[o], We2[o * 8 + o2], s);
        e2[o2] = tanhf(s);
    }
    float s3 = be3[0];
#pragma unroll
    for (int o2 = 0; o2 < 8; o2++) s3 = fmaf(e2[o2], We3[o2], s3);
    out[i] = s3;
}

// ---------------- launch ---------------------------------------------------
extern "C" void kernel_launch(void* const* d_in, const int* in_sizes, int n_in,
                              void* d_out, int out_size) {
    const float* x      = (const float*)d_in[0];
    const int*   agent  = (const int*)  d_in[1];
    const int*   nbr    = (const int*)  d_in[2];
    const float* Wl     = (const float*)d_in[3];
    const float* Wr     = (const float*)d_in[4];
    const float* attw   = (const float*)d_in[5];
    const float* bias   = (const float*)d_in[6];
    const float* Wg1    = (const float*)d_in[7];
    const float* bg1    = (const float*)d_in[8];
    const float* Wg2    = (const float*)d_in[9];
    const float* bg2    = (const float*)d_in[10];
    const float* We1    = (const float*)d_in[11];
    const float* be1    = (const float*)d_in[12];
    const float* We2    = (const float*)d_in[13];
    const float* be2    = (const float*)d_in[14];
    const float* We3    = (const float*)d_in[15];
    const float* be3    = (const float*)d_in[16];
    float* out = (float*)d_out;

    // reverse CSR of incoming edges + pool zeroing, one kernel
    csr_build_kernel<<<1, 1024>>>(nbr);

    // layer-0 xl projection into buffer A (fp16)
    xl0_kernel<<<NT / 256, 256>>>(x, Wl);

    // 4 fused GATv2 layers (xl buffers ping-pong A->B->A->B)
    gat_fused_kernel<0, true,  false><<<NT / 128, 128>>>(x, Wr,       attw,      bias,      Wl + 256);
    gat_fused_kernel<1, false, false><<<NT / 128, 128>>>(x, Wr + 256, attw + 16, bias + 16, Wl + 512);
    gat_fused_kernel<0, false, false><<<NT / 128, 128>>>(x, Wr + 512, attw + 32, bias + 32, Wl + 768);
    gat_fused_kernel<1, false, true ><<<NT / 128, 128>>>(x, Wr + 768, attw + 48, bias + 48, nullptr);

    // pooling + agg MLP, then edge scorer
    pool1_kernel<<<BB * 8, 256>>>();
    pool2_kernel<<<BB, 64>>>(Wg1, bg1, Wg2, bg2);
    scorer_kernel<<<(BB * 3 * DD + 127) / 128, 128>>>(agent, nbr,
                                                      We1, be1, We2, be2, We3, be3, out);
}

// round 6
// speedup vs baseline: 1.3149x; 1.3149x over previous
#include <cuda_runtime.h>
#include <math.h>

#define NB 8192
#define BB 64
#define DD 5
#define NE (NB*DD)      // 40960 neighbor edges
#define NT (NB*BB)      // 524288 (node, batch) rows
#define HC 16

// ---------------- device scratch (no runtime allocation allowed) ------------
__device__ float g_xl [(size_t)NT * HC];   // 33.5 MB, layout (n,b,hc)  (buffer A)
__device__ float g_xl2[(size_t)NT * HC];   // 33.5 MB                   (buffer B)
__device__ float g_h  [(size_t)NT * HC];   // 33.5 MB
__device__ float g_pool[BB * HC];
__device__ float g_agg[BB * 64];
__device__ int   g_cnt[NB];
__device__ int   g_off[NB + 1];
__device__ int   g_cur[NB];
__device__ int   g_csr[NE];

// ---------------- reverse-CSR construction (multi-block, fast) -------------
__global__ void zero_kernel() {
    int i = blockIdx.x * blockDim.x + threadIdx.x;
    if (i < NB) g_cnt[i] = 0;
    if (i < BB * HC) g_pool[i] = 0.f;
}

__global__ void count_kernel(const int* __restrict__ neighbors) {
    int e = blockIdx.x * blockDim.x + threadIdx.x;
    if (e < NE) atomicAdd(&g_cnt[neighbors[e]], 1);
}

__global__ void scan_kernel() {
    __shared__ int wsum[32];
    int t = threadIdx.x;
    int v[8];
    int s = 0;
#pragma unroll
    for (int i = 0; i < 8; i++) { v[i] = g_cnt[t * 8 + i]; s += v[i]; }
    unsigned lane = t & 31, wid = t >> 5;
    int x = s;
#pragma unroll
    for (int o = 1; o < 32; o <<= 1) {
        int y = __shfl_up_sync(0xffffffffu, x, o);
        if (lane >= (unsigned)o) x += y;
    }
    if (lane == 31) wsum[wid] = x;
    __syncthreads();
    if (wid == 0) {
        int w = wsum[lane];
#pragma unroll
        for (int o = 1; o < 32; o <<= 1) {
            int y = __shfl_up_sync(0xffffffffu, w, o);
            if (lane >= (unsigned)o) w += y;
        }
        wsum[lane] = w;
    }
    __syncthreads();
    int excl = x - s + (wid ? wsum[wid - 1] : 0);
    int run = excl;
#pragma unroll
    for (int i = 0; i < 8; i++) {
        g_off[t * 8 + i] = run;
        g_cur[t * 8 + i] = run;
        run += v[i];
    }
    if (t == 1023) g_off[NB] = run;
}

__global__ void fill_kernel(const int* __restrict__ neighbors) {
    int e = blockIdx.x * blockDim.x + threadIdx.x;
    if (e < NE) {
        int dst = neighbors[e];
        int pos = atomicAdd(&g_cur[dst], 1);
        g_csr[pos] = e / DD;   // source node of edge e
    }
}

// ---------------- layer-0 xl projection: g_xl = x @ Wl0 --------------------
__global__ __launch_bounds__(256)
void xl0_kernel(const float* __restrict__ xin, const float* __restrict__ Wl) {
    __shared__ float sW[256];
    int t = threadIdx.x;
    sW[t] = Wl[t];
    __syncthreads();

    int idx = blockIdx.x * 256 + t;      // n*64 + b
    int n = idx >> 6, b = idx & 63;
    const float4* p4 = (const float4*)(xin + ((size_t)b * NB + n) * HC);
    float in[16];
#pragma unroll
    for (int i = 0; i < 4; i++) {
        float4 v = __ldcs(p4 + i);                    // streaming read of x
        in[4 * i] = v.x; in[4 * i + 1] = v.y; in[4 * i + 2] = v.z; in[4 * i + 3] = v.w;
    }
    float ol[16];
#pragma unroll
    for (int o = 0; o < 16; o++) ol[o] = 0.f;
#pragma unroll
    for (int f = 0; f < 16; f++) {
        float a = in[f];
#pragma unroll
        for (int o = 0; o < 16; o++) ol[o] = fmaf(a, sW[f * 16 + o], ol[o]);
    }
    float4* pl = (float4*)(g_xl + (size_t)idx * HC);
#pragma unroll
    for (int i = 0; i < 4; i++)
        pl[i] = make_float4(ol[4 * i], ol[4 * i + 1], ol[4 * i + 2], ol[4 * i + 3]);
}

// ---------------- fused GATv2 layer, head-sliced ---------------------------
// Block = one node n (256 threads = 64 batches x 4 head-quarters).
// Each thread owns channels [hq*4, hq*4+4) of row (n,b).
// Plain-exp softmax (no max subtraction; logits are O(1)).
#define SH_STRIDE 20   // 64 rows x 20 floats: stride-20 avoids LDS bank conflicts

template <int IN, bool FIRST, bool LAST>
__global__ __launch_bounds__(256)
void gat2_kernel(const float* __restrict__ hin,   // used when FIRST: x in (b,n,f)
                 const float* __restrict__ Wr,
                 const float* __restrict__ attw,
                 const float* __restrict__ bias,
                 const float* __restrict__ Wln) { // next layer's Wl (null if LAST)
    __shared__ float sWr[256], sWln[256], satt[16], sbias[16];
    __shared__ float sh[64 * SH_STRIDE];
    int t = threadIdx.x;
    sWr[t] = Wr[t];
    if (!LAST) sWln[t] = Wln[t];
    if (t < 16) { satt[t] = attw[t]; sbias[t] = bias[t]; }

    const float* __restrict__ xlin  = (IN == 0) ? g_xl : g_xl2;
    float*       __restrict__ xlout = (IN == 0) ? g_xl2 : g_xl;

    int n  = blockIdx.x;
    int b  = t >> 2;
    int hq = t & 3;
    size_t idx = (size_t)n * BB + b;

    // ---- load own quarter of the h row, share row via smem ---------------
    float4 h4;
    if (FIRST) h4 = __ldcs((const float4*)(hin + ((size_t)b * NB + n) * HC) + hq);
    else       h4 = ((const float4*)(g_h + idx * HC))[hq];
    __syncthreads();                              // weights loaded
    *(float4*)&sh[b * SH_STRIDE + hq * 4] = h4;
    __syncthreads();

    // ---- xrv quarter: xrv[j] = sum_f h[f] * Wr[f][hq*4+j] -----------------
    float4 xr = make_float4(0.f, 0.f, 0.f, 0.f);
#pragma unroll
    for (int f = 0; f < 16; f++) {
        float hf = sh[b * SH_STRIDE + f];
        float4 w = *(const float4*)&sWr[f * 16 + hq * 4];
        xr.x = fmaf(hf, w.x, xr.x);
        xr.y = fmaf(hf, w.y, xr.y);
        xr.z = fmaf(hf, w.z, xr.z);
        xr.w = fmaf(hf, w.w, xr.w);
    }
    float4 aw = *(const float4*)&satt[hq * 4];

    // ---- self edge --------------------------------------------------------
    float4 v = ((const float4*)(xlin + idx * HC))[hq];
    float l, wgt, s;
    float4 acc;
    {
        float z;
        z = v.x + xr.x; l  = fmaxf(z, 0.2f * z) * aw.x;
        z = v.y + xr.y; l += fmaxf(z, 0.2f * z) * aw.y;
        z = v.z + xr.z; l += fmaxf(z, 0.2f * z) * aw.z;
        z = v.w + xr.w; l += fmaxf(z, 0.2f * z) * aw.w;
        wgt = __expf(l);
        s = wgt;
        acc = make_float4(wgt * v.x, wgt * v.y, wgt * v.z, wgt * v.w);
    }

    // ---- incoming-edge loop with 1-deep prefetch --------------------------
    int beg = g_off[n], end = g_off[n + 1];
    int boff = b * HC + hq * 4;
    float4 P = make_float4(0.f, 0.f, 0.f, 0.f);
    if (beg < end)
        P = *(const float4*)(xlin + (size_t)g_csr[beg] * (BB * HC) + boff);
    for (int e = beg; e < end; e++) {
        float4 Q = P;
        if (e + 1 < end)
            P = *(const float4*)(xlin + (size_t)g_csr[e + 1] * (BB * HC) + boff);
        float z;
        z = Q.x + xr.x; l  = fmaxf(z, 0.2f * z) * aw.x;
        z = Q.y + xr.y; l += fmaxf(z, 0.2f * z) * aw.y;
        z = Q.z + xr.z; l += fmaxf(z, 0.2f * z) * aw.z;
        z = Q.w + xr.w; l += fmaxf(z, 0.2f * z) * aw.w;
        wgt = __expf(l);
        s += wgt;
        acc.x = fmaf(wgt, Q.x, acc.x);
        acc.y = fmaf(wgt, Q.y, acc.y);
        acc.z = fmaf(wgt, Q.z, acc.z);
        acc.w = fmaf(wgt, Q.w, acc.w);
    }

    // ---- finalize quarter of the new h row --------------------------------
    float inv = 1.f / (s + 1e-16f);
    float4 bb4 = *(const float4*)&sbias[hq * 4];
    float4 o4 = make_float4(acc.x * inv + bb4.x, acc.y * inv + bb4.y,
                            acc.z * inv + bb4.z, acc.w * inv + bb4.w);
    ((float4*)(g_h + idx * HC))[hq] = o4;

    // ---- fused next-layer xl projection -----------------------------------
    if (!LAST) {
        __syncthreads();                          // xrv reads of sh complete
        *(float4*)&sh[b * SH_STRIDE + hq * 4] = o4;
        __syncthreads();
        float4 ol = make_float4(0.f, 0.f, 0.f, 0.f);
#pragma unroll
        for (int f = 0; f < 16; f++) {
            float hf = sh[b * SH_STRIDE + f];
            float4 w = *(const float4*)&sWln[f * 16 + hq * 4];
            ol.x = fmaf(hf, w.x, ol.x);
            ol.y = fmaf(hf, w.y, ol.y);
            ol.z = fmaf(hf, w.z, ol.z);
            ol.w = fmaf(hf, w.w, ol.w);
        }
        ((float4*)(xlout + idx * HC))[hq] = ol;
    }
}

// ---------------- mean-pool over nodes (phase 1: partial sums) -------------
__global__ __launch_bounds__(256)
void pool1_kernel() {
    int b = blockIdx.x >> 3;       // 64 batches
    int chunk = blockIdx.x & 7;    // 8 node chunks of 1024
    int t = threadIdx.x;
    int f = t & 15, g = t >> 4;    // 16 groups
    float sum = 0.f;
    int n0 = chunk * 1024 + g;
    for (int k = 0; k < 64; k++) {
        int n = n0 + k * 16;
        sum += g_h[((size_t)n * BB + b) * HC + f];
    }
    __shared__ float red[256];
    red[t] = sum;
    __syncthreads();
    for (int st = 128; st >= 16; st >>= 1) {
        if (t < st) red[t] += red[t + st];
        __syncthreads();
    }
    if (t < 16) atomicAdd(&g_pool[b * 16 + t], red[t]);
}

// ---------------- agg MLP (phase 2) ---------------------------------------
__global__ void pool2_kernel(const float* __restrict__ Wg1, const float* __restrict__ bg1,
                             const float* __restrict__ Wg2, const float* __restrict__ bg2) {
    int b = blockIdx.x;
    int t = threadIdx.x;   // 64 threads
    __shared__ float pool[16], g1[32];
    if (t < 16) pool[t] = g_pool[b * 16 + t] * (1.f / (float)NB);
    __syncthreads();
    if (t < 32) {
        float s = bg1[t];
#pragma unroll
        for (int ff = 0; ff < 16; ff++) s = fmaf(pool[ff], Wg1[ff * 32 + t], s);
        g1[t] = tanhf(s);
    }
    __syncthreads();
    float s = bg2[t];
#pragma unroll
    for (int k = 0; k < 32; k++) s = fmaf(g1[k], Wg2[k * 64 + t], s);
    g_agg[b * 64 + t] = tanhf(s);
}

// ---------------- edge scorer MLP (B x 3 x D items) ------------------------
__device__ __forceinline__ void acc_feat(float* acc1, const float* __restrict__ We1,
                                         int i, float val) {
#pragma unroll
    for (int o = 0; o < 16; o++)
        acc1[o] = fmaf(val, We1[i * 16 + o], acc1[o]);
}

__global__ void scorer_kernel(const int* __restrict__ agent_nodes,
                              const int* __restrict__ neighbors,
                              const float* __restrict__ We1, const float* __restrict__ be1,
                              const float* __restrict__ We2, const float* __restrict__ be2,
                              const float* __restrict__ We3, const float* __restrict__ be3,
                              float* __restrict__ out) {
    int i = blockIdx.x * blockDim.x + threadIdx.x;
    if (i >= BB * 3 * DD) return;
    int b = i / (3 * DD);
    int r = i % (3 * DD);
    int tk = r / DD;
    int d  = r % DD;
    int an = agent_nodes[b];
    int tg = neighbors[an * DD + d];

    float acc1[16];
#pragma unroll
    for (int o = 0; o < 16; o++) acc1[o] = be1[o];

#pragma unroll
    for (int ff = 0; ff < 16; ff++)                         // source features [0,16)
        acc_feat(acc1, We1, ff, g_h[((size_t)an * BB + b) * HC + ff]);
    acc_feat(acc1, We1, 16, tk == 0 ? 1.f : 0.f);           // token one-hot [16,19)
    acc_feat(acc1, We1, 17, tk == 1 ? 1.f : 0.f);
    acc_feat(acc1, We1, 18, tk == 2 ? 1.f : 0.f);
#pragma unroll
    for (int ff = 0; ff < 16; ff++)                         // target features [19,35)
        acc_feat(acc1, We1, 19 + ff, g_h[((size_t)tg * BB + b) * HC + ff]);
#pragma unroll
    for (int k = 0; k < 64; k++)                            // agg features [35,99)
        acc_feat(acc1, We1, 35 + k, g_agg[b * 64 + k]);

    float e1[16];
#pragma unroll
    for (int o = 0; o < 16; o++) e1[o] = tanhf(acc1[o]);

    float e2[8];
#pragma unroll
    for (int o2 = 0; o2 < 8; o2++) {
        float s = be2[o2];
#pragma unroll
        for (int o = 0; o < 16; o++) s = fmaf(e1[o], We2[o * 8 + o2], s);
        e2[o2] = tanhf(s);
    }
    float s3 = be3[0];
#pragma unroll
    for (int o2 = 0; o2 < 8; o2++) s3 = fmaf(e2[o2], We3[o2], s3);
    out[i] = s3;
}

// ---------------- launch ---------------------------------------------------
extern "C" void kernel_launch(void* const* d_in, const int* in_sizes, int n_in,
                              void* d_out, int out_size) {
    const float* x      = (const float*)d_in[0];
    const int*   agent  = (const int*)  d_in[1];
    const int*   nbr    = (const int*)  d_in[2];
    const float* Wl     = (const float*)d_in[3];
    const float* Wr     = (const float*)d_in[4];
    const float* attw   = (const float*)d_in[5];
    const float* bias   = (const float*)d_in[6];
    const float* Wg1    = (const float*)d_in[7];
    const float* bg1    = (const float*)d_in[8];
    const float* Wg2    = (const float*)d_in[9];
    const float* bg2    = (const float*)d_in[10];
    const float* We1    = (const float*)d_in[11];
    const float* be1    = (const float*)d_in[12];
    const float* We2    = (const float*)d_in[13];
    const float* be2    = (const float*)d_in[14];
    const float* We3    = (const float*)d_in[15];
    const float* be3    = (const float*)d_in[16];
    float* out = (float*)d_out;

    // reverse CSR of incoming edges (multi-block) + zero pool accumulators
    zero_kernel<<<32, 256>>>();
    count_kernel<<<(NE + 255) / 256, 256>>>(nbr);
    scan_kernel<<<1, 1024>>>();
    fill_kernel<<<(NE + 255) / 256, 256>>>(nbr);

    // layer-0 xl projection into buffer A
    xl0_kernel<<<NT / 256, 256>>>(x, Wl);

    // 4 fused GATv2 layers (xl buffers ping-pong A->B->A->B), 1 node/block
    gat2_kernel<0, true,  false><<<NB, 256>>>(x, Wr,       attw,      bias,      Wl + 256);
    gat2_kernel<1, false, false><<<NB, 256>>>(x, Wr + 256, attw + 16, bias + 16, Wl + 512);
    gat2_kernel<0, false, false><<<NB, 256>>>(x, Wr + 512, attw + 32, bias + 32, Wl + 768);
    gat2_kernel<1, false, true ><<<NB, 256>>>(x, Wr + 768, attw + 48, bias + 48, nullptr);

    // pooling + agg MLP, then edge scorer
    pool1_kernel<<<BB * 8, 256>>>();
    pool2_kernel<<<BB, 64>>>(Wg1, bg1, Wg2, bg2);
    scorer_kernel<<<(BB * 3 * DD + 127) / 128, 128>>>(agent, nbr,
                                                      We1, be1, We2, be2, We3, be3, out);
}

// round 7
// speedup vs baseline: 1.3382x; 1.0177x over previous
#include <cuda_runtime.h>
#include <math.h>

#define NB 8192
#define BB 64
#define DD 5
#define NE (NB*DD)      // 40960 neighbor edges
#define NT (NB*BB)      // 524288 (node, batch) rows
#define HC 16

// ---------------- device scratch (no runtime allocation allowed) ------------
__device__ float g_xlA[(size_t)NT * HC];   // 33.5 MB, layout (n,b,hc)
__device__ float g_xrA[(size_t)NT * HC];
__device__ float g_xlB[(size_t)NT * HC];
__device__ float g_xrB[(size_t)NT * HC];
__device__ float g_h  [(size_t)NT * HC];   // final-layer h only
__device__ float g_poolp[8 * BB * HC];     // pool partials (chunk, b, f)
__device__ int   g_cnt[NB];                // static zero-init; scan re-zeroes
__device__ int   g_off[NB + 1];
__device__ int   g_cur[NB];
__device__ int   g_csr[NE];

// ---------------- reverse-CSR construction --------------------------------
__global__ void count_kernel(const int* __restrict__ neighbors) {
    int e = blockIdx.x * blockDim.x + threadIdx.x;
    if (e < NE) atomicAdd(&g_cnt[neighbors[e]], 1);
}

// exclusive prefix of counts; seeds fill cursors; re-zeroes g_cnt so the next
// graph replay starts clean (deterministic across replays).
__global__ void scan_kernel() {
    __shared__ int wsum[32];
    int t = threadIdx.x;
    int v[8];
    int s = 0;
#pragma unroll
    for (int i = 0; i < 8; i++) {
        v[i] = g_cnt[t * 8 + i];
        g_cnt[t * 8 + i] = 0;          // reset for next replay
        s += v[i];
    }
    unsigned lane = t & 31, wid = t >> 5;
    int x = s;
#pragma unroll
    for (int o = 1; o < 32; o <<= 1) {
        int y = __shfl_up_sync(0xffffffffu, x, o);
        if (lane >= (unsigned)o) x += y;
    }
    if (lane == 31) wsum[wid] = x;
    __syncthreads();
    if (wid == 0) {
        int w = wsum[lane];
#pragma unroll
        for (int o = 1; o < 32; o <<= 1) {
            int y = __shfl_up_sync(0xffffffffu, w, o);
            if (lane >= (unsigned)o) w += y;
        }
        wsum[lane] = w;
    }
    __syncthreads();
    int excl = x - s + (wid ? wsum[wid - 1] : 0);
    int run = excl;
#pragma unroll
    for (int i = 0; i < 8; i++) {
        g_off[t * 8 + i] = run;
        g_cur[t * 8 + i] = run;
        run += v[i];
    }
    if (t == 1023) g_off[NB] = run;
}

__global__ void fill_kernel(const int* __restrict__ neighbors) {
    int e = blockIdx.x * blockDim.x + threadIdx.x;
    if (e < NE) {
        int dst = neighbors[e];
        int pos = atomicAdd(&g_cur[dst], 1);
        g_csr[pos] = e / DD;   // source node of edge e
    }
}

// ---------------- layer-0 projections: xl0 = x@Wl0, xr0 = x@Wr0 ------------
__global__ __launch_bounds__(256)
void proj0_kernel(const float* __restrict__ xin,
                  const float* __restrict__ Wl, const float* __restrict__ Wr) {
    __shared__ float sW[512];
    int t = threadIdx.x;
    sW[t]       = Wl[t];
    sW[256 + t] = Wr[t];
    __syncthreads();

    int idx = blockIdx.x * 256 + t;      // n*64 + b
    int n = idx >> 6, b = idx & 63;
    const float4* p4 = (const float4*)(xin + ((size_t)b * NB + n) * HC);
    float in[16];
#pragma unroll
    for (int i = 0; i < 4; i++) {
        float4 v = __ldcs(p4 + i);                    // streaming read of x
        in[4 * i] = v.x; in[4 * i + 1] = v.y; in[4 * i + 2] = v.z; in[4 * i + 3] = v.w;
    }
    float ol[16], orr[16];
#pragma unroll
    for (int o = 0; o < 16; o++) { ol[o] = 0.f; orr[o] = 0.f; }
#pragma unroll
    for (int f = 0; f < 16; f++) {
        float a = in[f];
#pragma unroll
        for (int o = 0; o < 16; o++) {
            ol[o]  = fmaf(a, sW[f * 16 + o], ol[o]);
            orr[o] = fmaf(a, sW[256 + f * 16 + o], orr[o]);
        }
    }
    float4* pl = (float4*)(g_xlA + (size_t)idx * HC);
    float4* pr = (float4*)(g_xrA + (size_t)idx * HC);
#pragma unroll
    for (int i = 0; i < 4; i++) {
        pl[i] = make_float4(ol[4 * i], ol[4 * i + 1], ol[4 * i + 2], ol[4 * i + 3]);
        pr[i] = make_float4(orr[4 * i], orr[4 * i + 1], orr[4 * i + 2], orr[4 * i + 3]);
    }
}

// ---------------- fused GATv2 layer, head-sliced, xr-materialized ----------
// Block = one node n (256 threads = 64 batches x 4 head-quarters).
// Reads xl_in/xr_in; writes xl_out/xr_out for the next layer (or h if LAST).
// Plain-exp softmax (logits are O(1); matches reference analytically).
template <int IN, bool LAST>
__global__ __launch_bounds__(256)
void gat3_kernel(const float* __restrict__ attw,
                 const float* __restrict__ bias,
                 const float* __restrict__ Wln,   // next layer's Wl (null if LAST)
                 const float* __restrict__ Wrn) { // next layer's Wr (null if LAST)
    __shared__ float sWl[256], sWr[256];
    int t = threadIdx.x;
    if (!LAST) { sWl[t] = Wln[t]; sWr[t] = Wrn[t]; __syncthreads(); }

    const float* __restrict__ xlin  = (IN == 0) ? g_xlA : g_xlB;
    const float* __restrict__ xrin  = (IN == 0) ? g_xrA : g_xrB;
    float*       __restrict__ xlout = (IN == 0) ? g_xlB : g_xlA;
    float*       __restrict__ xrout = (IN == 0) ? g_xrB : g_xrA;

    int n  = blockIdx.x;
    int b  = t >> 2;
    int hq = t & 3;
    size_t idx = (size_t)n * BB + b;

    float4 att4 = __ldg((const float4*)attw + hq);
    float4 xr   = ((const float4*)(xrin + idx * HC))[hq];

    // ---- self edge --------------------------------------------------------
    float4 v = ((const float4*)(xlin + idx * HC))[hq];
    float l, wgt, s;
    float4 acc;
    {
        float z;
        z = v.x + xr.x; l  = fmaxf(z, 0.2f * z) * att4.x;
        z = v.y + xr.y; l += fmaxf(z, 0.2f * z) * att4.y;
        z = v.z + xr.z; l += fmaxf(z, 0.2f * z) * att4.z;
        z = v.w + xr.w; l += fmaxf(z, 0.2f * z) * att4.w;
        wgt = __expf(l);
        s = wgt;
        acc = make_float4(wgt * v.x, wgt * v.y, wgt * v.z, wgt * v.w);
    }

    // ---- incoming-edge loop with 2-deep prefetch --------------------------
    int beg = g_off[n], end = g_off[n + 1];
    int boff = b * HC + hq * 4;
    float4 P0 = make_float4(0.f, 0.f, 0.f, 0.f);
    float4 P1 = P0;
    if (beg < end)
        P0 = *(const float4*)(xlin + (size_t)g_csr[beg] * (BB * HC) + boff);
    if (beg + 1 < end)
        P1 = *(const float4*)(xlin + (size_t)g_csr[beg + 1] * (BB * HC) + boff);
    for (int e = beg; e < end; e++) {
        float4 Q = P0;
        P0 = P1;
        if (e + 2 < end)
            P1 = *(const float4*)(xlin + (size_t)g_csr[e + 2] * (BB * HC) + boff);
        float z;
        z = Q.x + xr.x; l  = fmaxf(z, 0.2f * z) * att4.x;
        z = Q.y + xr.y; l += fmaxf(z, 0.2f * z) * att4.y;
        z = Q.z + xr.z; l += fmaxf(z, 0.2f * z) * att4.z;
        z = Q.w + xr.w; l += fmaxf(z, 0.2f * z) * att4.w;
        wgt = __expf(l);
        s += wgt;
        acc.x = fmaf(wgt, Q.x, acc.x);
        acc.y = fmaf(wgt, Q.y, acc.y);
        acc.z = fmaf(wgt, Q.z, acc.z);
        acc.w = fmaf(wgt, Q.w, acc.w);
    }

    // ---- finalize quarter of the new h row --------------------------------
    float inv = 1.f / (s + 1e-16f);
    float4 bb4 = __ldg((const float4*)bias + hq);
    float4 o4 = make_float4(acc.x * inv + bb4.x, acc.y * inv + bb4.y,
                            acc.z * inv + bb4.z, acc.w * inv + bb4.w);

    if (LAST) {
        ((float4*)(g_h + idx * HC))[hq] = o4;
        return;
    }

    // ---- next-layer projections via quad shuffle --------------------------
    // The 4 threads of batch-quad b hold the full 16-channel h row.
    float4 ol = make_float4(0.f, 0.f, 0.f, 0.f);
    float4 orr = ol;
    int lane = t & 31;
    int qbase = lane & ~3;
#pragma unroll
    for (int f = 0; f < 16; f++) {
        float src = (f & 3) == 0 ? o4.x : (f & 3) == 1 ? o4.y
                  : (f & 3) == 2 ? o4.z : o4.w;
        float hf = __shfl_sync(0xffffffffu, src, qbase | (f >> 2), 32);
        float4 wl = *(const float4*)&sWl[f * 16 + hq * 4];
        float4 wr = *(const float4*)&sWr[f * 16 + hq * 4];
        ol.x  = fmaf(hf, wl.x, ol.x);  ol.y  = fmaf(hf, wl.y, ol.y);
        ol.z  = fmaf(hf, wl.z, ol.z);  ol.w  = fmaf(hf, wl.w, ol.w);
        orr.x = fmaf(hf, wr.x, orr.x); orr.y = fmaf(hf, wr.y, orr.y);
        orr.z = fmaf(hf, wr.z, orr.z); orr.w = fmaf(hf, wr.w, orr.w);
    }
    ((float4*)(xlout + idx * HC))[hq] = ol;
    ((float4*)(xrout + idx * HC))[hq] = orr;
}

// ---------------- mean-pool over nodes (phase 1: partial sums) -------------
__global__ __launch_bounds__(256)
void pool1_kernel() {
    int b = blockIdx.x >> 3;       // 64 batches
    int chunk = blockIdx.x & 7;    // 8 node chunks of 1024
    int t = threadIdx.x;
    int f = t & 15, g = t >> 4;    // 16 groups
    float sum = 0.f;
    int n0 = chunk * 1024 + g;
    for (int k = 0; k < 64; k++) {
        int n = n0 + k * 16;
        sum += g_h[((size_t)n * BB + b) * HC + f];
    }
    __shared__ float red[256];
    red[t] = sum;
    __syncthreads();
    for (int st = 128; st >= 16; st >>= 1) {
        if (t < st) red[t] += red[t + st];
        __syncthreads();
    }
    if (t < 16) g_poolp[chunk * (BB * HC) + b * HC + t] = red[t];
}

// ---------------- agg MLP + edge scorer, one block per batch ---------------
__global__ __launch_bounds__(128)
void pool2_scorer_kernel(const int* __restrict__ agent_nodes,
                         const int* __restrict__ neighbors,
                         const float* __restrict__ Wg1, const float* __restrict__ bg1,
                         const float* __restrict__ Wg2, const float* __restrict__ bg2,
                         const float* __restrict__ We1, const float* __restrict__ be1,
                         const float* __restrict__ We2, const float* __restrict__ be2,
                         const float* __restrict__ We3, const float* __restrict__ be3,
                         float* __restrict__ out) {
    int b = blockIdx.x;
    int t = threadIdx.x;   // 128 threads
    __shared__ float pool[16], g1[32], agg[64];
    if (t < 16) {
        float s = 0.f;
#pragma unroll
        for (int c = 0; c < 8; c++) s += g_poolp[c * (BB * HC) + b * HC + t];
        pool[t] = s * (1.f / (float)NB);
    }
    __syncthreads();
    if (t < 32) {
        float s = bg1[t];
#pragma unroll
        for (int ff = 0; ff < 16; ff++) s = fmaf(pool[ff], Wg1[ff * 32 + t], s);
        g1[t] = tanhf(s);
    }
    __syncthreads();
    if (t < 64) {
        float s = bg2[t];
#pragma unroll
        for (int k = 0; k < 32; k++) s = fmaf(g1[k], Wg2[k * 64 + t], s);
        agg[t] = tanhf(s);
    }
    __syncthreads();

    if (t >= 3 * DD) return;          // 15 scorer items per batch
    int tk = t / DD;
    int d  = t % DD;
    int an = agent_nodes[b];
    int tg = neighbors[an * DD + d];

    float acc1[16];
#pragma unroll
    for (int o = 0; o < 16; o++) acc1[o] = be1[o];

#pragma unroll
    for (int ff = 0; ff < 16; ff++) {                       // source [0,16)
        float val = g_h[((size_t)an * BB + b) * HC + ff];
#pragma unroll
        for (int o = 0; o < 16; o++) acc1[o] = fmaf(val, We1[ff * 16 + o], acc1[o]);
    }
    {                                                       // token one-hot [16,19)
        int i = 16 + tk;
#pragma unroll
        for (int o = 0; o < 16; o++) acc1[o] += We1[i * 16 + o];
    }
#pragma unroll
    for (int ff = 0; ff < 16; ff++) {                       // target [19,35)
        float val = g_h[((size_t)tg * BB + b) * HC + ff];
#pragma unroll
        for (int o = 0; o < 16; o++) acc1[o] = fmaf(val, We1[(19 + ff) * 16 + o], acc1[o]);
    }
#pragma unroll
    for (int k = 0; k < 64; k++) {                          // agg [35,99)
        float val = agg[k];
#pragma unroll
        for (int o = 0; o < 16; o++) acc1[o] = fmaf(val, We1[(35 + k) * 16 + o], acc1[o]);
    }

    float e1[16];
#pragma unroll
    for (int o = 0; o < 16; o++) e1[o] = tanhf(acc1[o]);

    float e2[8];
#pragma unroll
    for (int o2 = 0; o2 < 8; o2++) {
        float s = be2[o2];
#pragma unroll
        for (int o = 0; o < 16; o++) s = fmaf(e1[o], We2[o * 8 + o2], s);
        e2[o2] = tanhf(s);
    }
    float s3 = be3[0];
#pragma unroll
    for (int o2 = 0; o2 < 8; o2++) s3 = fmaf(e2[o2], We3[o2], s3);
    out[b * (3 * DD) + t] = s3;
}

// ---------------- launch ---------------------------------------------------
extern "C" void kernel_launch(void* const* d_in, const int* in_sizes, int n_in,
                              void* d_out, int out_size) {
    const float* x      = (const float*)d_in[0];
    const int*   agent  = (const int*)  d_in[1];
    const int*   nbr    = (const int*)  d_in[2];
    const float* Wl     = (const float*)d_in[3];
    const float* Wr     = (const float*)d_in[4];
    const float* attw   = (const float*)d_in[5];
    const float* bias   = (const float*)d_in[6];
    const float* Wg1    = (const float*)d_in[7];
    const float* bg1    = (const float*)d_in[8];
    const float* Wg2    = (const float*)d_in[9];
    const float* bg2    = (const float*)d_in[10];
    const float* We1    = (const float*)d_in[11];
    const float* be1    = (const float*)d_in[12];
    const float* We2    = (const float*)d_in[13];
    const float* be2    = (const float*)d_in[14];
    const float* We3    = (const float*)d_in[15];
    const float* be3    = (const float*)d_in[16];
    float* out = (float*)d_out;

    // reverse CSR (g_cnt is zero on entry: static init / re-zeroed by scan)
    count_kernel<<<(NE + 255) / 256, 256>>>(nbr);
    scan_kernel<<<1, 1024>>>();
    fill_kernel<<<(NE + 255) / 256, 256>>>(nbr);

    // layer-0 projections into buffer A
    proj0_kernel<<<NT / 256, 256>>>(x, Wl, Wr);

    // 4 fused GATv2 layers (buffers ping-pong A->B->A->B), 1 node/block
    gat3_kernel<0, false><<<NB, 256>>>(attw,      bias,      Wl + 256, Wr + 256);
    gat3_kernel<1, false><<<NB, 256>>>(attw + 16, bias + 16, Wl + 512, Wr + 512);
    gat3_kernel<0, false><<<NB, 256>>>(attw + 32, bias + 32, Wl + 768, Wr + 768);
    gat3_kernel<1, true ><<<NB, 256>>>(attw + 48, bias + 48, nullptr,  nullptr);

    // pooling partials, then agg-MLP + scorer fused (one block per batch)
    pool1_kernel<<<BB * 8, 256>>>();
    pool2_scorer_kernel<<<BB, 128>>>(agent, nbr, Wg1, bg1, Wg2, bg2,
                                     We1, be1, We2, be2, We3, be3, out);
}

// round 8
// speedup vs baseline: 1.3938x; 1.0416x over previous
#include <cuda_runtime.h>
#include <math.h>

#define NB 8192
#define BB 64
#define DD 5
#define NE (NB*DD)      // 40960 neighbor edges
#define NT (NB*BB)      // 524288 (node, batch) rows
#define HC 16

// ---------------- device scratch (no runtime allocation allowed) ------------
__device__ float g_xlA[(size_t)NT * HC];   // 33.5 MB, layout (n,b,hc)
__device__ float g_xrA[(size_t)NT * HC];
__device__ float g_xlB[(size_t)NT * HC];
__device__ float g_xrB[(size_t)NT * HC];
__device__ float g_h  [(size_t)NT * HC];   // final-layer h only
__device__ float g_poolp[8 * BB * HC];     // pool partials (chunk, b, f)
__device__ int   g_cnt[NB];                // static zero-init; scan re-zeroes
__device__ int   g_off[NB + 1];
__device__ int   g_cur[NB];
__device__ int   g_csr[NE];

// ---------------- CSR scan (re-zeroes counts for next graph replay) --------
__global__ void scan_kernel() {
    __shared__ int wsum[32];
    int t = threadIdx.x;
    int v[8];
    int s = 0;
#pragma unroll
    for (int i = 0; i < 8; i++) {
        v[i] = g_cnt[t * 8 + i];
        g_cnt[t * 8 + i] = 0;          // reset for next replay
        s += v[i];
    }
    unsigned lane = t & 31, wid = t >> 5;
    int x = s;
#pragma unroll
    for (int o = 1; o < 32; o <<= 1) {
        int y = __shfl_up_sync(0xffffffffu, x, o);
        if (lane >= (unsigned)o) x += y;
    }
    if (lane == 31) wsum[wid] = x;
    __syncthreads();
    if (wid == 0) {
        int w = wsum[lane];
#pragma unroll
        for (int o = 1; o < 32; o <<= 1) {
            int y = __shfl_up_sync(0xffffffffu, w, o);
            if (lane >= (unsigned)o) w += y;
        }
        wsum[lane] = w;
    }
    __syncthreads();
    int excl = x - s + (wid ? wsum[wid - 1] : 0);
    int run = excl;
#pragma unroll
    for (int i = 0; i < 8; i++) {
        g_off[t * 8 + i] = run;
        g_cur[t * 8 + i] = run;
        run += v[i];
    }
    if (t == 1023) g_off[NB] = run;
}

__global__ void fill_kernel(const int* __restrict__ neighbors) {
    int e = blockIdx.x * blockDim.x + threadIdx.x;
    if (e < NE) {
        int dst = neighbors[e];
        int pos = atomicAdd(&g_cur[dst], 1);
        g_csr[pos] = e / DD;   // source node of edge e
    }
}

// ---------------- layer-0 projections (quad-sliced, coalesced) -------------
// Thread = (row, quarter): quad of 4 threads owns one (n,b) row.
// Reads x[(b,n,:)] as 4x16B contiguous per quad; stores xl/xr coalesced.
// Also performs the CSR degree count (fused; first 160 blocks carry edges).
__global__ __launch_bounds__(256)
void proj0_kernel(const float* __restrict__ xin,
                  const float* __restrict__ neighbors_i,
                  const float* __restrict__ Wl, const float* __restrict__ Wr) {
    __shared__ float sWl[256], sWr[256];
    int t = threadIdx.x;
    sWl[t] = Wl[t];
    sWr[t] = Wr[t];

    // fused CSR count
    int e = blockIdx.x * 256 + t;
    if (e < NE) atomicAdd(&g_cnt[((const int*)neighbors_i)[e]], 1);
    __syncthreads();

    int row = blockIdx.x * 64 + (t >> 2);   // row = n*64 + b
    int hq  = t & 3;
    int n = row >> 6, b = row & 63;

    float4 xq = __ldcs((const float4*)(xin + ((size_t)b * NB + n) * HC) + hq);

    float4 ol  = make_float4(0.f, 0.f, 0.f, 0.f);
    float4 orr = ol;
    int qbase = (t & 31) & ~3;
#pragma unroll
    for (int f = 0; f < 16; f++) {
        float src = (f & 3) == 0 ? xq.x : (f & 3) == 1 ? xq.y
                  : (f & 3) == 2 ? xq.z : xq.w;
        float hf = __shfl_sync(0xffffffffu, src, qbase | (f >> 2), 32);
        float4 wl = *(const float4*)&sWl[f * 16 + hq * 4];
        float4 wr = *(const float4*)&sWr[f * 16 + hq * 4];
        ol.x  = fmaf(hf, wl.x, ol.x);  ol.y  = fmaf(hf, wl.y, ol.y);
        ol.z  = fmaf(hf, wl.z, ol.z);  ol.w  = fmaf(hf, wl.w, ol.w);
        orr.x = fmaf(hf, wr.x, orr.x); orr.y = fmaf(hf, wr.y, orr.y);
        orr.z = fmaf(hf, wr.z, orr.z); orr.w = fmaf(hf, wr.w, orr.w);
    }
    ((float4*)(g_xlA + (size_t)row * HC))[hq] = ol;
    ((float4*)(g_xrA + (size_t)row * HC))[hq] = orr;
}

// ---------------- fused GATv2 layer, head-sliced, xr-materialized ----------
// Block = one node n (256 threads = 64 batches x 4 head-quarters).
// Plain-exp softmax via exp2 with log2(e) folded into the attention weights.
template <int IN, bool LAST>
__global__ __launch_bounds__(256)
void gat3_kernel(const float* __restrict__ attw,
                 const float* __restrict__ bias,
                 const float* __restrict__ Wln,   // next layer's Wl (null if LAST)
                 const float* __restrict__ Wrn) { // next layer's Wr (null if LAST)
    __shared__ float sWl[256], sWr[256];
    int t = threadIdx.x;
    if (!LAST) { sWl[t] = Wln[t]; sWr[t] = Wrn[t]; __syncthreads(); }

    const float* __restrict__ xlin  = (IN == 0) ? g_xlA : g_xlB;
    const float* __restrict__ xrin  = (IN == 0) ? g_xrA : g_xrB;
    float*       __restrict__ xlout = (IN == 0) ? g_xlB : g_xlA;
    float*       __restrict__ xrout = (IN == 0) ? g_xrB : g_xrA;

    int n  = blockIdx.x;
    int b  = t >> 2;
    int hq = t & 3;
    size_t idx = (size_t)n * BB + b;

    const float LOG2E = 1.4426950408889634f;
    float4 att4 = __ldg((const float4*)attw + hq);
    att4.x *= LOG2E; att4.y *= LOG2E; att4.z *= LOG2E; att4.w *= LOG2E;
    float4 xr = ((const float4*)(xrin + idx * HC))[hq];

    // ---- self edge --------------------------------------------------------
    float4 v = ((const float4*)(xlin + idx * HC))[hq];
    float l, wgt, s;
    float4 acc;
    {
        float z;
        z = v.x + xr.x; l  = fmaxf(z, 0.2f * z) * att4.x;
        z = v.y + xr.y; l += fmaxf(z, 0.2f * z) * att4.y;
        z = v.z + xr.z; l += fmaxf(z, 0.2f * z) * att4.z;
        z = v.w + xr.w; l += fmaxf(z, 0.2f * z) * att4.w;
        wgt = exp2f(l);
        s = wgt;
        acc = make_float4(wgt * v.x, wgt * v.y, wgt * v.z, wgt * v.w);
    }

    // ---- incoming-edge loop with 2-deep prefetch --------------------------
    int beg = g_off[n], end = g_off[n + 1];
    int boff = b * HC + hq * 4;
    float4 P0 = make_float4(0.f, 0.f, 0.f, 0.f);
    float4 P1 = P0;
    if (beg < end)
        P0 = *(const float4*)(xlin + (size_t)g_csr[beg] * (BB * HC) + boff);
    if (beg + 1 < end)
        P1 = *(const float4*)(xlin + (size_t)g_csr[beg + 1] * (BB * HC) + boff);
    for (int e = beg; e < end; e++) {
        float4 Q = P0;
        P0 = P1;
        if (e + 2 < end)
            P1 = *(const float4*)(xlin + (size_t)g_csr[e + 2] * (BB * HC) + boff);
        float z;
        z = Q.x + xr.x; l  = fmaxf(z, 0.2f * z) * att4.x;
        z = Q.y + xr.y; l += fmaxf(z, 0.2f * z) * att4.y;
        z = Q.z + xr.z; l += fmaxf(z, 0.2f * z) * att4.z;
        z = Q.w + xr.w; l += fmaxf(z, 0.2f * z) * att4.w;
        wgt = exp2f(l);
        s += wgt;
        acc.x = fmaf(wgt, Q.x, acc.x);
        acc.y = fmaf(wgt, Q.y, acc.y);
        acc.z = fmaf(wgt, Q.z, acc.z);
        acc.w = fmaf(wgt, Q.w, acc.w);
    }

    // ---- finalize quarter of the new h row --------------------------------
    float inv = 1.f / (s + 1e-16f);
    float4 bb4 = __ldg((const float4*)bias + hq);
    float4 o4 = make_float4(acc.x * inv + bb4.x, acc.y * inv + bb4.y,
                            acc.z * inv + bb4.z, acc.w * inv + bb4.w);

    if (LAST) {
        ((float4*)(g_h + idx * HC))[hq] = o4;
        return;
    }

    // ---- next-layer projections via quad shuffle --------------------------
    float4 ol = make_float4(0.f, 0.f, 0.f, 0.f);
    float4 orr = ol;
    int qbase = (t & 31) & ~3;
#pragma unroll
    for (int f = 0; f < 16; f++) {
        float src = (f & 3) == 0 ? o4.x : (f & 3) == 1 ? o4.y
                  : (f & 3) == 2 ? o4.z : o4.w;
        float hf = __shfl_sync(0xffffffffu, src, qbase | (f >> 2), 32);
        float4 wl = *(const float4*)&sWl[f * 16 + hq * 4];
        float4 wr = *(const float4*)&sWr[f * 16 + hq * 4];
        ol.x  = fmaf(hf, wl.x, ol.x);  ol.y  = fmaf(hf, wl.y, ol.y);
        ol.z  = fmaf(hf, wl.z, ol.z);  ol.w  = fmaf(hf, wl.w, ol.w);
        orr.x = fmaf(hf, wr.x, orr.x); orr.y = fmaf(hf, wr.y, orr.y);
        orr.z = fmaf(hf, wr.z, orr.z); orr.w = fmaf(hf, wr.w, orr.w);
    }
    ((float4*)(xlout + idx * HC))[hq] = ol;
    ((float4*)(xrout + idx * HC))[hq] = orr;
}

// ---------------- mean-pool over nodes (phase 1: partial sums) -------------
__global__ __launch_bounds__(256)
void pool1_kernel() {
    int b = blockIdx.x >> 3;       // 64 batches
    int chunk = blockIdx.x & 7;    // 8 node chunks of 1024
    int t = threadIdx.x;
    int f = t & 15, g = t >> 4;    // 16 groups
    float sum = 0.f;
    int n0 = chunk * 1024 + g;
    for (int k = 0; k < 64; k++) {
        int n = n0 + k * 16;
        sum += g_h[((size_t)n * BB + b) * HC + f];
    }
    __shared__ float red[256];
    red[t] = sum;
    __syncthreads();
    for (int st = 128; st >= 16; st >>= 1) {
        if (t < st) red[t] += red[t + st];
        __syncthreads();
    }
    if (t < 16) g_poolp[chunk * (BB * HC) + b * HC + t] = red[t];
}

// ---------------- agg MLP + edge scorer, one block per batch ---------------
__global__ __launch_bounds__(128)
void pool2_scorer_kernel(const int* __restrict__ agent_nodes,
                         const int* __restrict__ neighbors,
                         const float* __restrict__ Wg1, const float* __restrict__ bg1,
                         const float* __restrict__ Wg2, const float* __restrict__ bg2,
                         const float* __restrict__ We1, const float* __restrict__ be1,
                         const float* __restrict__ We2, const float* __restrict__ be2,
                         const float* __restrict__ We3, const float* __restrict__ be3,
                         float* __restrict__ out) {
    int b = blockIdx.x;
    int t = threadIdx.x;   // 128 threads
    __shared__ float pool[16], g1[32], agg[64];
    if (t < 16) {
        float s = 0.f;
#pragma unroll
        for (int c = 0; c < 8; c++) s += g_poolp[c * (BB * HC) + b * HC + t];
        pool[t] = s * (1.f / (float)NB);
    }
    __syncthreads();
    if (t < 32) {
        float s = bg1[t];
#pragma unroll
        for (int ff = 0; ff < 16; ff++) s = fmaf(pool[ff], Wg1[ff * 32 + t], s);
        g1[t] = tanhf(s);
    }
    __syncthreads();
    if (t < 64) {
        float s = bg2[t];
#pragma unroll
        for (int k = 0; k < 32; k++) s = fmaf(g1[k], Wg2[k * 64 + t], s);
        agg[t] = tanhf(s);
    }
    __syncthreads();

    if (t >= 3 * DD) return;          // 15 scorer items per batch
    int tk = t / DD;
    int d  = t % DD;
    int an = agent_nodes[b];
    int tg = neighbors[an * DD + d];

    float acc1[16];
#pragma unroll
    for (int o = 0; o < 16; o++) acc1[o] = be1[o];

#pragma unroll
    for (int ff = 0; ff < 16; ff++) {                       // source [0,16)
        float val = g_h[((size_t)an * BB + b) * HC + ff];
#pragma unroll
        for (int o = 0; o < 16; o++) acc1[o] = fmaf(val, We1[ff * 16 + o], acc1[o]);
    }
    {                                                       // token one-hot [16,19)
        int i = 16 + tk;
#pragma unroll
        for (int o = 0; o < 16; o++) acc1[o] += We1[i * 16 + o];
    }
#pragma unroll
    for (int ff = 0; ff < 16; ff++) {                       // target [19,35)
        float val = g_h[((size_t)tg * BB + b) * HC + ff];
#pragma unroll
        for (int o = 0; o < 16; o++) acc1[o] = fmaf(val, We1[(19 + ff) * 16 + o], acc1[o]);
    }
#pragma unroll
    for (int k = 0; k < 64; k++) {                          // agg [35,99)
        float val = agg[k];
#pragma unroll
        for (int o = 0; o < 16; o++) acc1[o] = fmaf(val, We1[(35 + k) * 16 + o], acc1[o]);
    }

    float e1[16];
#pragma unroll
    for (int o = 0; o < 16; o++) e1[o] = tanhf(acc1[o]);

    float e2[8];
#pragma unroll
    for (int o2 = 0; o2 < 8; o2++) {
        float s = be2[o2];
#pragma unroll
        for (int o = 0; o < 16; o++) s = fmaf(e1[o], We2[o * 8 + o2], s);
        e2[o2] = tanhf(s);
    }
    float s3 = be3[0];
#pragma unroll
    for (int o2 = 0; o2 < 8; o2++) s3 = fmaf(e2[o2], We3[o2], s3);
    out[b * (3 * DD) + t] = s3;
}

// ---------------- launch ---------------------------------------------------
extern "C" void kernel_launch(void* const* d_in, const int* in_sizes, int n_in,
                              void* d_out, int out_size) {
    const float* x      = (const float*)d_in[0];
    const int*   agent  = (const int*)  d_in[1];
    const int*   nbr    = (const int*)  d_in[2];
    const float* Wl     = (const float*)d_in[3];
    const float* Wr     = (const float*)d_in[4];
    const float* attw   = (const float*)d_in[5];
    const float* bias   = (const float*)d_in[6];
    const float* Wg1    = (const float*)d_in[7];
    const float* bg1    = (const float*)d_in[8];
    const float* Wg2    = (const float*)d_in[9];
    const float* bg2    = (const float*)d_in[10];
    const float* We1    = (const float*)d_in[11];
    const float* be1    = (const float*)d_in[12];
    const float* We2    = (const float*)d_in[13];
    const float* be2    = (const float*)d_in[14];
    const float* We3    = (const float*)d_in[15];
    const float* be3    = (const float*)d_in[16];
    float* out = (float*)d_out;

    // layer-0 projections (with fused CSR degree count)
    proj0_kernel<<<NT / 64, 256>>>(x, (const float*)nbr, Wl, Wr);
    scan_kernel<<<1, 1024>>>();
    fill_kernel<<<(NE + 255) / 256, 256>>>(nbr);

    // 4 fused GATv2 layers (buffers ping-pong A->B->A->B), 1 node/block
    gat3_kernel<0, false><<<NB, 256>>>(attw,      bias,      Wl + 256, Wr + 256);
    gat3_kernel<1, false><<<NB, 256>>>(attw + 16, bias + 16, Wl + 512, Wr + 512);
    gat3_kernel<0, false><<<NB, 256>>>(attw + 32, bias + 32, Wl + 768, Wr + 768);
    gat3_kernel<1, true ><<<NB, 256>>>(attw + 48, bias + 48, nullptr,  nullptr);

    // pooling partials, then agg-MLP + scorer fused (one block per batch)
    pool1_kernel<<<BB * 8, 256>>>();
    pool2_scorer_kernel<<<BB, 128>>>(agent, nbr, Wg1, bg1, Wg2, bg2,
                                     We1, be1, We2, be2, We3, be3, out);
}

// round 9
// speedup vs baseline: 1.5270x; 1.0955x over previous
#include <cuda_runtime.h>
#include <cuda_fp16.h>
#include <math.h>

#define NB 8192
#define BB 64
#define DD 5
#define NE (NB*DD)      // 40960 neighbor edges
#define NT (NB*BB)      // 524288 (node, batch) rows
#define HC 16

// ---------------- device scratch (no runtime allocation allowed) ------------
__device__ __half g_xlA[(size_t)NT * HC];   // 16.8 MB, layout (n,b,hc) fp16
__device__ __half g_xrA[(size_t)NT * HC];
__device__ __half g_xlB[(size_t)NT * HC];
__device__ __half g_xrB[(size_t)NT * HC];
__device__ float  g_h  [(size_t)NT * HC];   // final-layer h only (fp32)
__device__ float  g_poolp[8 * BB * HC];     // pool partials (chunk, b, f)
__device__ int    g_cnt[NB];                // static zero-init; scan re-zeroes
__device__ int    g_off[NB + 1];
__device__ int    g_cur[NB];
__device__ int    g_csr[NE];

// ---------------- fp16 quarter-row <-> fp32 helpers ------------------------
__device__ __forceinline__ float4 q_h2f(uint2 u) {
    float2 f0 = __half22float2(*reinterpret_cast<__half2*>(&u.x));
    float2 f1 = __half22float2(*reinterpret_cast<__half2*>(&u.y));
    return make_float4(f0.x, f0.y, f1.x, f1.y);
}
__device__ __forceinline__ uint2 q_f2h(float4 v) {
    __half2 h0 = __floats2half2_rn(v.x, v.y);
    __half2 h1 = __floats2half2_rn(v.z, v.w);
    uint2 u;
    u.x = *reinterpret_cast<unsigned*>(&h0);
    u.y = *reinterpret_cast<unsigned*>(&h1);
    return u;
}

// ---------------- CSR scan (re-zeroes counts for next graph replay) --------
__global__ void scan_kernel() {
    __shared__ int wsum[32];
    int t = threadIdx.x;
    int v[8];
    int s = 0;
#pragma unroll
    for (int i = 0; i < 8; i++) {
        v[i] = g_cnt[t * 8 + i];
        g_cnt[t * 8 + i] = 0;          // reset for next replay
        s += v[i];
    }
    unsigned lane = t & 31, wid = t >> 5;
    int x = s;
#pragma unroll
    for (int o = 1; o < 32; o <<= 1) {
        int y = __shfl_up_sync(0xffffffffu, x, o);
        if (lane >= (unsigned)o) x += y;
    }
    if (lane == 31) wsum[wid] = x;
    __syncthreads();
    if (wid == 0) {
        int w = wsum[lane];
#pragma unroll
        for (int o = 1; o < 32; o <<= 1) {
            int y = __shfl_up_sync(0xffffffffu, w, o);
            if (lane >= (unsigned)o) w += y;
        }
        wsum[lane] = w;
    }
    __syncthreads();
    int excl = x - s + (wid ? wsum[wid - 1] : 0);
    int run = excl;
#pragma unroll
    for (int i = 0; i < 8; i++) {
        g_off[t * 8 + i] = run;
        g_cur[t * 8 + i] = run;
        run += v[i];
    }
    if (t == 1023) g_off[NB] = run;
}

__global__ void fill_kernel(const int* __restrict__ neighbors) {
    int e = blockIdx.x * blockDim.x + threadIdx.x;
    if (e < NE) {
        int dst = neighbors[e];
        int pos = atomicAdd(&g_cur[dst], 1);
        g_csr[pos] = e / DD;   // source node of edge e
    }
}

// ---------------- layer-0 projections (quad-sliced, coalesced, fp16 out) ---
__global__ __launch_bounds__(256)
void proj0_kernel(const float* __restrict__ xin,
                  const float* __restrict__ neighbors_i,
                  const float* __restrict__ Wl, const float* __restrict__ Wr) {
    __shared__ float sWl[256], sWr[256];
    int t = threadIdx.x;
    sWl[t] = Wl[t];
    sWr[t] = Wr[t];

    // fused CSR count
    int e = blockIdx.x * 256 + t;
    if (e < NE) atomicAdd(&g_cnt[((const int*)neighbors_i)[e]], 1);
    __syncthreads();

    int row = blockIdx.x * 64 + (t >> 2);   // row = n*64 + b
    int hq  = t & 3;
    int n = row >> 6, b = row & 63;

    float4 xq = __ldcs((const float4*)(xin + ((size_t)b * NB + n) * HC) + hq);

    float4 ol  = make_float4(0.f, 0.f, 0.f, 0.f);
    float4 orr = ol;
    int qbase = (t & 31) & ~3;
#pragma unroll
    for (int f = 0; f < 16; f++) {
        float src = (f & 3) == 0 ? xq.x : (f & 3) == 1 ? xq.y
                  : (f & 3) == 2 ? xq.z : xq.w;
        float hf = __shfl_sync(0xffffffffu, src, qbase | (f >> 2), 32);
        float4 wl = *(const float4*)&sWl[f * 16 + hq * 4];
        float4 wr = *(const float4*)&sWr[f * 16 + hq * 4];
        ol.x  = fmaf(hf, wl.x, ol.x);  ol.y  = fmaf(hf, wl.y, ol.y);
        ol.z  = fmaf(hf, wl.z, ol.z);  ol.w  = fmaf(hf, wl.w, ol.w);
        orr.x = fmaf(hf, wr.x, orr.x); orr.y = fmaf(hf, wr.y, orr.y);
        orr.z = fmaf(hf, wr.z, orr.z); orr.w = fmaf(hf, wr.w, orr.w);
    }
    ((uint2*)(g_xlA + (size_t)row * HC))[hq] = q_f2h(ol);
    ((uint2*)(g_xrA + (size_t)row * HC))[hq] = q_f2h(orr);
}

// ---------------- fused GATv2 layer, head-sliced, fp16 buffers -------------
// Block = one node n (256 threads = 64 batches x 4 head-quarters).
// Plain-exp softmax via exp2 with log2(e) folded into attention weights.
template <int IN, bool LAST>
__global__ __launch_bounds__(256)
void gat3_kernel(const float* __restrict__ attw,
                 const float* __restrict__ bias,
                 const float* __restrict__ Wln,   // next layer's Wl (null if LAST)
                 const float* __restrict__ Wrn) { // next layer's Wr (null if LAST)
    __shared__ float sWl[256], sWr[256];
    int t = threadIdx.x;
    if (!LAST) { sWl[t] = Wln[t]; sWr[t] = Wrn[t]; __syncthreads(); }

    const __half* __restrict__ xlin  = (IN == 0) ? g_xlA : g_xlB;
    const __half* __restrict__ xrin  = (IN == 0) ? g_xrA : g_xrB;
    __half*       __restrict__ xlout = (IN == 0) ? g_xlB : g_xlA;
    __half*       __restrict__ xrout = (IN == 0) ? g_xrB : g_xrA;

    int n  = blockIdx.x;
    int b  = t >> 2;
    int hq = t & 3;
    size_t idx = (size_t)n * BB + b;

    const float LOG2E = 1.4426950408889634f;
    float4 att4 = __ldg((const float4*)attw + hq);
    att4.x *= LOG2E; att4.y *= LOG2E; att4.z *= LOG2E; att4.w *= LOG2E;
    float4 xr = q_h2f(((const uint2*)(xrin + idx * HC))[hq]);

    // ---- self edge --------------------------------------------------------
    float4 v = q_h2f(((const uint2*)(xlin + idx * HC))[hq]);
    float l, wgt, s;
    float4 acc;
    {
        float z;
        z = v.x + xr.x; l  = fmaxf(z, 0.2f * z) * att4.x;
        z = v.y + xr.y; l += fmaxf(z, 0.2f * z) * att4.y;
        z = v.z + xr.z; l += fmaxf(z, 0.2f * z) * att4.z;
        z = v.w + xr.w; l += fmaxf(z, 0.2f * z) * att4.w;
        wgt = exp2f(l);
        s = wgt;
        acc = make_float4(wgt * v.x, wgt * v.y, wgt * v.z, wgt * v.w);
    }

    // ---- incoming-edge loop with 2-deep prefetch --------------------------
    int beg = g_off[n], end = g_off[n + 1];
    int boff = b * HC + hq * 4;            // in half units
    uint2 P0 = make_uint2(0u, 0u), P1 = P0;
    if (beg < end)
        P0 = *(const uint2*)(xlin + (size_t)g_csr[beg] * (BB * HC) + boff);
    if (beg + 1 < end)
        P1 = *(const uint2*)(xlin + (size_t)g_csr[beg + 1] * (BB * HC) + boff);
    for (int e = beg; e < end; e++) {
        float4 Q = q_h2f(P0);
        P0 = P1;
        if (e + 2 < end)
            P1 = *(const uint2*)(xlin + (size_t)g_csr[e + 2] * (BB * HC) + boff);
        float z;
        z = Q.x + xr.x; l  = fmaxf(z, 0.2f * z) * att4.x;
        z = Q.y + xr.y; l += fmaxf(z, 0.2f * z) * att4.y;
        z = Q.z + xr.z; l += fmaxf(z, 0.2f * z) * att4.z;
        z = Q.w + xr.w; l += fmaxf(z, 0.2f * z) * att4.w;
        wgt = exp2f(l);
        s += wgt;
        acc.x = fmaf(wgt, Q.x, acc.x);
        acc.y = fmaf(wgt, Q.y, acc.y);
        acc.z = fmaf(wgt, Q.z, acc.z);
        acc.w = fmaf(wgt, Q.w, acc.w);
    }

    // ---- finalize quarter of the new h row --------------------------------
    float inv = 1.f / (s + 1e-16f);
    float4 bb4 = __ldg((const float4*)bias + hq);
    float4 o4 = make_float4(acc.x * inv + bb4.x, acc.y * inv + bb4.y,
                            acc.z * inv + bb4.z, acc.w * inv + bb4.w);

    if (LAST) {
        ((float4*)(g_h + idx * HC))[hq] = o4;
        return;
    }

    // ---- next-layer projections via quad shuffle --------------------------
    float4 ol = make_float4(0.f, 0.f, 0.f, 0.f);
    float4 orr = ol;
    int qbase = (t & 31) & ~3;
#pragma unroll
    for (int f = 0; f < 16; f++) {
        float src = (f & 3) == 0 ? o4.x : (f & 3) == 1 ? o4.y
                  : (f & 3) == 2 ? o4.z : o4.w;
        float hf = __shfl_sync(0xffffffffu, src, qbase | (f >> 2), 32);
        float4 wl = *(const float4*)&sWl[f * 16 + hq * 4];
        float4 wr = *(const float4*)&sWr[f * 16 + hq * 4];
        ol.x  = fmaf(hf, wl.x, ol.x);  ol.y  = fmaf(hf, wl.y, ol.y);
        ol.z  = fmaf(hf, wl.z, ol.z);  ol.w  = fmaf(hf, wl.w, ol.w);
        orr.x = fmaf(hf, wr.x, orr.x); orr.y = fmaf(hf, wr.y, orr.y);
        orr.z = fmaf(hf, wr.z, orr.z); orr.w = fmaf(hf, wr.w, orr.w);
    }
    ((uint2*)(xlout + idx * HC))[hq] = q_f2h(ol);
    ((uint2*)(xrout + idx * HC))[hq] = q_f2h(orr);
}

// ---------------- mean-pool over nodes (phase 1: partial sums) -------------
__global__ __launch_bounds__(256)
void pool1_kernel() {
    int b = blockIdx.x >> 3;       // 64 batches
    int chunk = blockIdx.x & 7;    // 8 node chunks of 1024
    int t = threadIdx.x;
    int f = t & 15, g = t >> 4;    // 16 groups
    float sum = 0.f;
    int n0 = chunk * 1024 + g;
    for (int k = 0; k < 64; k++) {
        int n = n0 + k * 16;
        sum += g_h[((size_t)n * BB + b) * HC + f];
    }
    __shared__ float red[256];
    red[t] = sum;
    __syncthreads();
    for (int st = 128; st >= 16; st >>= 1) {
        if (t < st) red[t] += red[t + st];
        __syncthreads();
    }
    if (t < 16) g_poolp[chunk * (BB * HC) + b * HC + t] = red[t];
}

// ---------------- agg MLP + edge scorer, one block per batch ---------------
__global__ __launch_bounds__(128)
void pool2_scorer_kernel(const int* __restrict__ agent_nodes,
                         const int* __restrict__ neighbors,
                         const float* __restrict__ Wg1, const float* __restrict__ bg1,
                         const float* __restrict__ Wg2, const float* __restrict__ bg2,
                         const float* __restrict__ We1, const float* __restrict__ be1,
                         const float* __restrict__ We2, const float* __restrict__ be2,
                         const float* __restrict__ We3, const float* __restrict__ be3,
                         float* __restrict__ out) {
    int b = blockIdx.x;
    int t = threadIdx.x;   // 128 threads
    __shared__ float pool[16], g1[32], agg[64];
    if (t < 16) {
        float s = 0.f;
#pragma unroll
        for (int c = 0; c < 8; c++) s += g_poolp[c * (BB * HC) + b * HC + t];
        pool[t] = s * (1.f / (float)NB);
    }
    __syncthreads();
    if (t < 32) {
        float s = bg1[t];
#pragma unroll
        for (int ff = 0; ff < 16; ff++) s = fmaf(pool[ff], Wg1[ff * 32 + t], s);
        g1[t] = tanhf(s);
    }
    __syncthreads();
    if (t < 64) {
        float s = bg2[t];
#pragma unroll
        for (int k = 0; k < 32; k++) s = fmaf(g1[k], Wg2[k * 64 + t], s);
        agg[t] = tanhf(s);
    }
    __syncthreads();

    if (t >= 3 * DD) return;          // 15 scorer items per batch
    int tk = t / DD;
    int d  = t % DD;
    int an = agent_nodes[b];
    int tg = neighbors[an * DD + d];

    float acc1[16];
#pragma unroll
    for (int o = 0; o < 16; o++) acc1[o] = be1[o];

#pragma unroll
    for (int ff = 0; ff < 16; ff++) {                       // source [0,16)
        float val = g_h[((size_t)an * BB + b) * HC + ff];
#pragma unroll
        for (int o = 0; o < 16; o++) acc1[o] = fmaf(val, We1[ff * 16 + o], acc1[o]);
    }
    {                                                       // token one-hot [16,19)
        int i = 16 + tk;
#pragma unroll
        for (int o = 0; o < 16; o++) acc1[o] += We1[i * 16 + o];
    }
#pragma unroll
    for (int ff = 0; ff < 16; ff++) {                       // target [19,35)
        float val = g_h[((size_t)tg * BB + b) * HC + ff];
#pragma unroll
        for (int o = 0; o < 16; o++) acc1[o] = fmaf(val, We1[(19 + ff) * 16 + o], acc1[o]);
    }
#pragma unroll
    for (int k = 0; k < 64; k++) {                          // agg [35,99)
        float val = agg[k];
#pragma unroll
        for (int o = 0; o < 16; o++) acc1[o] = fmaf(val, We1[(35 + k) * 16 + o], acc1[o]);
    }

    float e1[16];
#pragma unroll
    for (int o = 0; o < 16; o++) e1[o] = tanhf(acc1[o]);

    float e2[8];
#pragma unroll
    for (int o2 = 0; o2 < 8; o2++) {
        float s = be2[o2];
#pragma unroll
        for (int o = 0; o < 16; o++) s = fmaf(e1[o], We2[o * 8 + o2], s);
        e2[o2] = tanhf(s);
    }
    float s3 = be3[0];
#pragma unroll
    for (int o2 = 0; o2 < 8; o2++) s3 = fmaf(e2[o2], We3[o2], s3);
    out[b * (3 * DD) + t] = s3;
}

// ---------------- launch ---------------------------------------------------
extern "C" void kernel_launch(void* const* d_in, const int* in_sizes, int n_in,
                              void* d_out, int out_size) {
    const float* x      = (const float*)d_in[0];
    const int*   agent  = (const int*)  d_in[1];
    const int*   nbr    = (const int*)  d_in[2];
    const float* Wl     = (const float*)d_in[3];
    const float* Wr     = (const float*)d_in[4];
    const float* attw   = (const float*)d_in[5];
    const float* bias   = (const float*)d_in[6];
    const float* Wg1    = (const float*)d_in[7];
    const float* bg1    = (const float*)d_in[8];
    const float* Wg2    = (const float*)d_in[9];
    const float* bg2    = (const float*)d_in[10];
    const float* We1    = (const float*)d_in[11];
    const float* be1    = (const float*)d_in[12];
    const float* We2    = (const float*)d_in[13];
    const float* be2    = (const float*)d_in[14];
    const float* We3    = (const float*)d_in[15];
    const float* be3    = (const float*)d_in[16];
    float* out = (float*)d_out;

    // layer-0 projections (with fused CSR degree count)
    proj0_kernel<<<NT / 64, 256>>>(x, (const float*)nbr, Wl, Wr);
    scan_kernel<<<1, 1024>>>();
    fill_kernel<<<(NE + 255) / 256, 256>>>(nbr);

    // 4 fused GATv2 layers (buffers ping-pong A->B->A->B), 1 node/block
    gat3_kernel<0, false><<<NB, 256>>>(attw,      bias,      Wl + 256, Wr + 256);
    gat3_kernel<1, false><<<NB, 256>>>(attw + 16, bias + 16, Wl + 512, Wr + 512);
    gat3_kernel<0, false><<<NB, 256>>>(attw + 32, bias + 32, Wl + 768, Wr + 768);
    gat3_kernel<1, true ><<<NB, 256>>>(attw + 48, bias + 48, nullptr,  nullptr);

    // pooling partials, then agg-MLP + scorer fused (one block per batch)
    pool1_kernel<<<BB * 8, 256>>>();
    pool2_scorer_kernel<<<BB, 128>>>(agent, nbr, Wg1, bg1, Wg2, bg2,
                                     We1, be1, We2, be2, We3, be3, out);
}